// round 4
// baseline (speedup 1.0000x reference)
#include <cuda_runtime.h>
#include <cstdint>

#define N_NODES_MAX 100000
#define OUT_DIM 128
#define IN_DIM 256

// Scratch for H = X @ W^T + b  (51.2 MB, device global per harness rules)
__device__ float g_H[(size_t)N_NODES_MAX * OUT_DIM];

// packed f32x2 fma (sm_100+)
__device__ __forceinline__ unsigned long long fma2(
    unsigned long long a, unsigned long long b, unsigned long long c)
{
    unsigned long long d;
    asm("fma.rn.f32x2 %0, %1, %2, %3;" : "=l"(d) : "l"(a), "l"(b), "l"(c));
    return d;
}

__device__ __forceinline__ unsigned long long dup2(float w)
{
    unsigned long long d;
    asm("mov.b64 %0, {%1, %1};" : "=l"(d) : "f"(w));
    return d;
}

// ---------------------------------------------------------------------------
// GEMM: H[M,128] = X[M,256] @ W[128,256]^T + b[128]
// Block = 256 threads. Tile: BM=128 rows, BN=128, BK=32.
// smem k-major: sX[k][r], sW[k][c], stride 136 (16B-aligned rows).
// Per-thread microtile: 8 rows x 8 cols => 1.0 smem-byte per MAC
// (vs 1.5 before). Accumulate as 4 row-pairs x 8 cols packed f32x2.
// ---------------------------------------------------------------------------
__global__ __launch_bounds__(256) void gcn_gemm_kernel(
    const float* __restrict__ X,
    const float* __restrict__ W,
    const float* __restrict__ bias,
    int M)
{
    __shared__ float sX[32 * 136];   // [k][r] 17.4 KB
    __shared__ float sW[32 * 136];   // [k][c] 17.4 KB

    const int tid = threadIdx.x;
    const int tx  = tid & 15;        // cols tx*8 .. tx*8+7
    const int ty  = tid >> 4;        // rows ty*8 .. ty*8+7
    const int rowBase = blockIdx.x * 128;

    // acc2[i2][j]: row-pair i2 (rows ty*8+2*i2, +1), col tx*8+j
    unsigned long long acc2[4][8];
#pragma unroll
    for (int i = 0; i < 4; ++i)
#pragma unroll
        for (int j = 0; j < 8; ++j) acc2[i][j] = 0ull;

    for (int k0 = 0; k0 < IN_DIM; k0 += 32) {
        // ---- load X tile: 128 rows x 32 k, transpose into sX[k][r] ----
#pragma unroll
        for (int it = 0; it < 4; ++it) {
            int idx = tid + it * 256;          // 0..1023 (128 rows * 8 float4)
            int r   = idx >> 3;
            int k4  = (idx & 7) << 2;
            int row = rowBase + r;
            float4 v = make_float4(0.f, 0.f, 0.f, 0.f);
            if (row < M)
                v = *(const float4*)(X + (size_t)row * IN_DIM + k0 + k4);
            sX[(k4 + 0) * 136 + r] = v.x;
            sX[(k4 + 1) * 136 + r] = v.y;
            sX[(k4 + 2) * 136 + r] = v.z;
            sX[(k4 + 3) * 136 + r] = v.w;
        }
        // ---- load W tile: 128 cols x 32 k, transpose into sW[k][c] ----
#pragma unroll
        for (int it = 0; it < 4; ++it) {
            int idx = tid + it * 256;
            int c   = idx >> 3;
            int k4  = (idx & 7) << 2;
            float4 v = *(const float4*)(W + (size_t)c * IN_DIM + k0 + k4);
            sW[(k4 + 0) * 136 + c] = v.x;
            sW[(k4 + 1) * 136 + c] = v.y;
            sW[(k4 + 2) * 136 + c] = v.z;
            sW[(k4 + 3) * 136 + c] = v.w;
        }
        __syncthreads();

#pragma unroll
        for (int k = 0; k < 32; ++k) {
            ulonglong2 aLo = *(const ulonglong2*)&sX[k * 136 + ty * 8];
            ulonglong2 aHi = *(const ulonglong2*)&sX[k * 136 + ty * 8 + 4];
            float4 wA = *(const float4*)&sW[k * 136 + tx * 8];
            float4 wB = *(const float4*)&sW[k * 136 + tx * 8 + 4];
            unsigned long long a2[4] = {aLo.x, aLo.y, aHi.x, aHi.y};
            unsigned long long w2[8] = {dup2(wA.x), dup2(wA.y), dup2(wA.z), dup2(wA.w),
                                        dup2(wB.x), dup2(wB.y), dup2(wB.z), dup2(wB.w)};
#pragma unroll
            for (int i = 0; i < 4; ++i)
#pragma unroll
                for (int j = 0; j < 8; ++j)
                    acc2[i][j] = fma2(a2[i], w2[j], acc2[i][j]);
        }
        __syncthreads();
    }

    // ---- epilogue: unpack, add bias, store to g_H ----
    float4 bA = *(const float4*)(bias + tx * 8);
    float4 bB = *(const float4*)(bias + tx * 8 + 4);
    float bv[8] = {bA.x, bA.y, bA.z, bA.w, bB.x, bB.y, bB.z, bB.w};
#pragma unroll
    for (int i2 = 0; i2 < 4; ++i2) {
        int row0 = rowBase + ty * 8 + 2 * i2;
        float lo[8], hi[8];
#pragma unroll
        for (int j = 0; j < 8; ++j) {
            lo[j] = __uint_as_float((unsigned)acc2[i2][j]) + bv[j];
            hi[j] = __uint_as_float((unsigned)(acc2[i2][j] >> 32)) + bv[j];
        }
        if (row0 < M) {
            float* p = g_H + (size_t)row0 * OUT_DIM + tx * 8;
            *(float4*)(p)     = make_float4(lo[0], lo[1], lo[2], lo[3]);
            *(float4*)(p + 4) = make_float4(lo[4], lo[5], lo[6], lo[7]);
        }
        if (row0 + 1 < M) {
            float* p = g_H + (size_t)(row0 + 1) * OUT_DIM + tx * 8;
            *(float4*)(p)     = make_float4(hi[0], hi[1], hi[2], hi[3]);
            *(float4*)(p + 4) = make_float4(hi[4], hi[5], hi[6], hi[7]);
        }
    }
}

// ---------------------------------------------------------------------------
// Edge scatter: out[row] += val * H[col].
// 4 edges per warp (batched for MLP=4): indices loaded up front, 4
// independent gathers in flight, then 4 RED.128 reductions per lane.
// ---------------------------------------------------------------------------
#define EDGES_PER_WARP 4

__global__ __launch_bounds__(256) void gcn_scatter_kernel(
    const int*   __restrict__ edge_row,
    const int*   __restrict__ edge_col,
    const float* __restrict__ edge_val,
    float*       __restrict__ out,
    int E)
{
    int warp = (int)((blockIdx.x * (unsigned)blockDim.x + threadIdx.x) >> 5);
    int lane = threadIdx.x & 31;
    int base = warp * EDGES_PER_WARP;
    if (base >= E) return;

    int   r[EDGES_PER_WARP], c[EDGES_PER_WARP];
    float v[EDGES_PER_WARP];
    int nb = min(EDGES_PER_WARP, E - base);

#pragma unroll
    for (int j = 0; j < EDGES_PER_WARP; ++j) {
        int e = base + (j < nb ? j : 0);
        r[j] = __ldg(edge_row + e);
        c[j] = __ldg(edge_col + e);
        v[j] = (j < nb) ? __ldg(edge_val + e) : 0.f;
    }

    float4 h[EDGES_PER_WARP];
#pragma unroll
    for (int j = 0; j < EDGES_PER_WARP; ++j)
        h[j] = *(const float4*)(g_H + (size_t)c[j] * OUT_DIM + lane * 4);

#pragma unroll
    for (int j = 0; j < EDGES_PER_WARP; ++j) {
        float* o = out + (size_t)r[j] * OUT_DIM + lane * 4;
        asm volatile("red.global.add.v4.f32 [%0], {%1, %2, %3, %4};"
                     :: "l"(o), "f"(v[j] * h[j].x), "f"(v[j] * h[j].y),
                        "f"(v[j] * h[j].z), "f"(v[j] * h[j].w)
                     : "memory");
    }
}

// ---------------------------------------------------------------------------
// Launch. Input order (metadata): X, edge_row, edge_col, edge_val, W, b.
// ---------------------------------------------------------------------------
extern "C" void kernel_launch(void* const* d_in, const int* in_sizes, int n_in,
                              void* d_out, int out_size)
{
    const float* X  = (const float*)d_in[0];
    const int*   er = (const int*)d_in[1];
    const int*   ec = (const int*)d_in[2];
    const float* ev = (const float*)d_in[3];
    const float* W  = (const float*)d_in[4];
    const float* b  = (const float*)d_in[5];
    float*      out = (float*)d_out;

    const int M = in_sizes[0] / IN_DIM;   // 100000
    const int E = in_sizes[3];            // 1600000

    cudaMemsetAsync(d_out, 0, (size_t)out_size * sizeof(float));

    gcn_gemm_kernel<<<(M + 127) / 128, 256>>>(X, W, b, M);

    // 4 edges/warp, 8 warps/block -> 32 edges per block
    int blocks = (E + 31) / 32;
    gcn_scatter_kernel<<<blocks, 256>>>(er, ec, ev, out, E);
}

// round 5
// speedup vs baseline: 1.3078x; 1.3078x over previous
#include <cuda_runtime.h>
#include <cstdint>

#define N_NODES_MAX 100000
#define OUT_DIM 128
#define IN_DIM 256

// Scratch for H = X @ W^T + b  (51.2 MB, device global per harness rules)
__device__ float g_H[(size_t)N_NODES_MAX * OUT_DIM];

// packed f32x2 fma (sm_100+)
__device__ __forceinline__ unsigned long long fma2(
    unsigned long long a, unsigned long long b, unsigned long long c)
{
    unsigned long long d;
    asm("fma.rn.f32x2 %0, %1, %2, %3;" : "=l"(d) : "l"(a), "l"(b), "l"(c));
    return d;
}

__device__ __forceinline__ unsigned long long dup2(float w)
{
    unsigned long long d;
    asm("mov.b64 %0, {%1, %1};" : "=l"(d) : "f"(w));
    return d;
}

// ---------------------------------------------------------------------------
// GEMM: H[M,128] = X[M,256] @ W[128,256]^T + b[128]
// Block = 256 threads. Tile: BM=64, BN=128, BK=32. Microtile 8x4 (f32x2 pairs).
// smem k-major, XOR-swizzled: element (k, r) lives at k*STRIDE + (r ^ (k&28)).
//  - transpose stores: banks = (r ^ k4) mod 32 -> all 32 distinct, conflict-free
//  - reads: sX broadcast per warp; sW bijective permutation, conflict-free
// Global loads for tile k0+32 are staged in registers during compute of k0.
// ---------------------------------------------------------------------------
__global__ __launch_bounds__(256) void gcn_gemm_kernel(
    const float* __restrict__ X,
    const float* __restrict__ W,
    const float* __restrict__ bias,
    int M)
{
    __shared__ float sX[32 * 64];    // 8 KB, [k][r^swz]
    __shared__ float sW[32 * 128];   // 16 KB, [k][c^swz]

    const int tid = threadIdx.x;
    const int tx  = tid & 31;        // cols tx*4 .. tx*4+3
    const int ty  = tid >> 5;        // rows ty*8 .. ty*8+7
    const int rowBase = blockIdx.x * 64;

    // per-thread tile-load coordinates (fixed across k0 iterations)
    const int xr0 = tid >> 3;              // it=0: row-local 0..31
    const int xr1 = (tid + 256) >> 3;      // it=1: row-local 32..63
    const int xk4 = (tid & 7) << 2;        // k-local 0,4,..,28

    unsigned long long acc2[4][4];
#pragma unroll
    for (int i = 0; i < 4; ++i)
#pragma unroll
        for (int j = 0; j < 4; ++j) acc2[i][j] = 0ull;

    // ---- prefetch tile k0 = 0 into registers ----
    float4 xv[2], wv[4];
    {
        int row0 = rowBase + xr0, row1 = rowBase + xr1;
        xv[0] = (row0 < M) ? *(const float4*)(X + (size_t)row0 * IN_DIM + xk4)
                           : make_float4(0.f, 0.f, 0.f, 0.f);
        xv[1] = (row1 < M) ? *(const float4*)(X + (size_t)row1 * IN_DIM + xk4)
                           : make_float4(0.f, 0.f, 0.f, 0.f);
#pragma unroll
        for (int it = 0; it < 4; ++it) {
            int c = (tid + it * 256) >> 3;
            wv[it] = *(const float4*)(W + (size_t)c * IN_DIM + xk4);
        }
    }

    for (int k0 = 0; k0 < IN_DIM; k0 += 32) {
        // ---- store staged tile to swizzled smem ----
        {
            float vx0[4] = {xv[0].x, xv[0].y, xv[0].z, xv[0].w};
            float vx1[4] = {xv[1].x, xv[1].y, xv[1].z, xv[1].w};
#pragma unroll
            for (int j = 0; j < 4; ++j) {
                sX[(xk4 + j) * 64 + (xr0 ^ xk4)] = vx0[j];
                sX[(xk4 + j) * 64 + (xr1 ^ xk4)] = vx1[j];
            }
#pragma unroll
            for (int it = 0; it < 4; ++it) {
                int c = (tid + it * 256) >> 3;
                float vw[4] = {wv[it].x, wv[it].y, wv[it].z, wv[it].w};
#pragma unroll
                for (int j = 0; j < 4; ++j)
                    sW[(xk4 + j) * 128 + (c ^ xk4)] = vw[j];
            }
        }
        __syncthreads();

        // ---- prefetch next tile (overlaps with compute below) ----
        if (k0 + 32 < IN_DIM) {
            int kk = k0 + 32 + xk4;
            int row0 = rowBase + xr0, row1 = rowBase + xr1;
            xv[0] = (row0 < M) ? *(const float4*)(X + (size_t)row0 * IN_DIM + kk)
                               : make_float4(0.f, 0.f, 0.f, 0.f);
            xv[1] = (row1 < M) ? *(const float4*)(X + (size_t)row1 * IN_DIM + kk)
                               : make_float4(0.f, 0.f, 0.f, 0.f);
#pragma unroll
            for (int it = 0; it < 4; ++it) {
                int c = (tid + it * 256) >> 3;
                wv[it] = *(const float4*)(W + (size_t)c * IN_DIM + kk);
            }
        }

        // ---- compute ----
#pragma unroll
        for (int k = 0; k < 32; ++k) {
            int m = k & 28;
            ulonglong2 aLo = *(const ulonglong2*)&sX[k * 64 + ((ty * 8) ^ m)];
            ulonglong2 aHi = *(const ulonglong2*)&sX[k * 64 + ((ty * 8 + 4) ^ m)];
            float4 w4 = *(const float4*)&sW[k * 128 + ((tx * 4) ^ m)];
            unsigned long long a2[4] = {aLo.x, aLo.y, aHi.x, aHi.y};
            unsigned long long w2[4] = {dup2(w4.x), dup2(w4.y), dup2(w4.z), dup2(w4.w)};
#pragma unroll
            for (int i = 0; i < 4; ++i) {
                acc2[i][0] = fma2(a2[i], w2[0], acc2[i][0]);
                acc2[i][1] = fma2(a2[i], w2[1], acc2[i][1]);
                acc2[i][2] = fma2(a2[i], w2[2], acc2[i][2]);
                acc2[i][3] = fma2(a2[i], w2[3], acc2[i][3]);
            }
        }
        __syncthreads();
    }

    // ---- epilogue: unpack, add bias, store to g_H ----
    float4 bv = *(const float4*)(bias + tx * 4);
#pragma unroll
    for (int i2 = 0; i2 < 4; ++i2) {
        int row0 = rowBase + ty * 8 + 2 * i2;
        float4 lo, hi;
        lo.x = __uint_as_float((unsigned)acc2[i2][0]) + bv.x;
        lo.y = __uint_as_float((unsigned)acc2[i2][1]) + bv.y;
        lo.z = __uint_as_float((unsigned)acc2[i2][2]) + bv.z;
        lo.w = __uint_as_float((unsigned)acc2[i2][3]) + bv.w;
        hi.x = __uint_as_float((unsigned)(acc2[i2][0] >> 32)) + bv.x;
        hi.y = __uint_as_float((unsigned)(acc2[i2][1] >> 32)) + bv.y;
        hi.z = __uint_as_float((unsigned)(acc2[i2][2] >> 32)) + bv.z;
        hi.w = __uint_as_float((unsigned)(acc2[i2][3] >> 32)) + bv.w;
        if (row0 < M)
            *(float4*)(g_H + (size_t)row0 * OUT_DIM + tx * 4) = lo;
        if (row0 + 1 < M)
            *(float4*)(g_H + (size_t)(row0 + 1) * OUT_DIM + tx * 4) = hi;
    }
}

// ---------------------------------------------------------------------------
// Edge scatter: out[row] += val * H[col]. 4 edges per warp (MLP=4),
// RED.128 vectorized reductions. At the L2 roofline (~145us).
// ---------------------------------------------------------------------------
#define EDGES_PER_WARP 4

__global__ __launch_bounds__(256) void gcn_scatter_kernel(
    const int*   __restrict__ edge_row,
    const int*   __restrict__ edge_col,
    const float* __restrict__ edge_val,
    float*       __restrict__ out,
    int E)
{
    int warp = (int)((blockIdx.x * (unsigned)blockDim.x + threadIdx.x) >> 5);
    int lane = threadIdx.x & 31;
    int base = warp * EDGES_PER_WARP;
    if (base >= E) return;

    int   r[EDGES_PER_WARP], c[EDGES_PER_WARP];
    float v[EDGES_PER_WARP];
    int nb = min(EDGES_PER_WARP, E - base);

#pragma unroll
    for (int j = 0; j < EDGES_PER_WARP; ++j) {
        int e = base + (j < nb ? j : 0);
        r[j] = __ldg(edge_row + e);
        c[j] = __ldg(edge_col + e);
        v[j] = (j < nb) ? __ldg(edge_val + e) : 0.f;
    }

    float4 h[EDGES_PER_WARP];
#pragma unroll
    for (int j = 0; j < EDGES_PER_WARP; ++j)
        h[j] = *(const float4*)(g_H + (size_t)c[j] * OUT_DIM + lane * 4);

#pragma unroll
    for (int j = 0; j < EDGES_PER_WARP; ++j) {
        float* o = out + (size_t)r[j] * OUT_DIM + lane * 4;
        asm volatile("red.global.add.v4.f32 [%0], {%1, %2, %3, %4};"
                     :: "l"(o), "f"(v[j] * h[j].x), "f"(v[j] * h[j].y),
                        "f"(v[j] * h[j].z), "f"(v[j] * h[j].w)
                     : "memory");
    }
}

// ---------------------------------------------------------------------------
// Launch. Input order (metadata): X, edge_row, edge_col, edge_val, W, b.
// ---------------------------------------------------------------------------
extern "C" void kernel_launch(void* const* d_in, const int* in_sizes, int n_in,
                              void* d_out, int out_size)
{
    const float* X  = (const float*)d_in[0];
    const int*   er = (const int*)d_in[1];
    const int*   ec = (const int*)d_in[2];
    const float* ev = (const float*)d_in[3];
    const float* W  = (const float*)d_in[4];
    const float* b  = (const float*)d_in[5];
    float*      out = (float*)d_out;

    const int M = in_sizes[0] / IN_DIM;   // 100000
    const int E = in_sizes[3];            // 1600000

    cudaMemsetAsync(d_out, 0, (size_t)out_size * sizeof(float));

    gcn_gemm_kernel<<<(M + 63) / 64, 256>>>(X, W, b, M);

    int blocks = (E + EDGES_PER_WARP * 8 - 1) / (EDGES_PER_WARP * 8);
    gcn_scatter_kernel<<<blocks, 256>>>(er, ec, ev, out, E);
}

// round 7
// speedup vs baseline: 1.5957x; 1.2201x over previous
#include <cuda_runtime.h>
#include <cuda_bf16.h>
#include <cstdint>

#define N_NODES_MAX 100000
#define OUT_DIM 128
#define IN_DIM 256

// Scratch for H = X @ W^T + b  (51.2 MB, device global per harness rules)
__device__ float g_H[(size_t)N_NODES_MAX * OUT_DIM];

// ===========================================================================
// bf16 split helpers
// ===========================================================================
// hi/lo bf16 split of a float pair, packed as bf16x2 words (low element in
// low 16 bits, matching mma fragment packing).
__device__ __forceinline__ void split2(float a, float b,
                                       uint32_t& hi, uint32_t& lo) {
    __nv_bfloat16 ha = __float2bfloat16_rn(a);
    __nv_bfloat16 hb = __float2bfloat16_rn(b);
    __nv_bfloat16 la = __float2bfloat16_rn(a - __bfloat162float(ha));
    __nv_bfloat16 lb = __float2bfloat16_rn(b - __bfloat162float(hb));
    hi = (uint32_t)__bfloat16_as_ushort(ha)
       | ((uint32_t)__bfloat16_as_ushort(hb) << 16);
    lo = (uint32_t)__bfloat16_as_ushort(la)
       | ((uint32_t)__bfloat16_as_ushort(lb) << 16);
}

// warp mma: D[16x8] += A[16x16] * B[16x8], bf16 in, fp32 accum (sm_80+ baseline)
__device__ __forceinline__ void mma_bf16(float* d, const uint32_t* a,
                                         uint32_t b0, uint32_t b1) {
    asm volatile(
        "mma.sync.aligned.m16n8k16.row.col.f32.bf16.bf16.f32 "
        "{%0,%1,%2,%3}, {%4,%5,%6,%7}, {%8,%9}, {%0,%1,%2,%3};"
        : "+f"(d[0]), "+f"(d[1]), "+f"(d[2]), "+f"(d[3])
        : "r"(a[0]), "r"(a[1]), "r"(a[2]), "r"(a[3]), "r"(b0), "r"(b1));
}

// ===========================================================================
// GEMM: H[M,128] = X[M,256] @ W[128,256]^T + b
// CTA = 256 threads (8 warps). CTA tile M=128, N=128, K chunked by 64.
// 3-term bf16 split: D = Xhi*Whi + Xhi*Wlo + Xlo*Whi (~1e-5 rel err).
//
// SMEM tiles stored in FRAGMENT ORDER (atom, kstep, reg, lane), lane-minor:
//   A: addr = (atom_m*4 + kstep)*136 + reg*34 + lane   (4 regs, pad->34)
//   B: addr = (atom_n*4 + kstep)*72  + reg*36 + lane   (2 regs, pad->36)
// Writers: STS.32 banks all-distinct per warp (verified: uniform +
// {0,2,4,6}[l&3] + 4*(l>>2)). Readers: lane-consecutive LDS.32, conflict-free.
//
// Warp w owns m-atom w (16 rows), all 16 n-atoms. D = 16 atoms x 4 f32.
// ===========================================================================
#define BK 64
#define NCHUNK (IN_DIM / BK)

// word offsets into dynamic smem (uint32_t units)
#define SM_AHI 0
#define SM_ALO 4352
#define SM_BHI 8704
#define SM_BLO 13312
#define SM_WORDS 17920           // 71680 bytes

__global__ __launch_bounds__(256) void gcn_gemm_tc(
    const float* __restrict__ X,
    const float* __restrict__ W,
    const float* __restrict__ bias,
    int M)
{
    extern __shared__ uint32_t smw[];
    const int tid = threadIdx.x;
    const int w   = tid >> 5;        // warp 0..7 = m-atom
    const int l   = tid & 31;
    const int rowBase = blockIdx.x * 128;

    float d[16][4];
#pragma unroll
    for (int na = 0; na < 16; ++na)
#pragma unroll
        for (int j = 0; j < 4; ++j) d[na][j] = 0.f;

    // writer-thread invariants
    const int wr_rl   = l >> 2;              // rr&7 (row/n low bits)
    const int wr_kk4  = (l & 3) * 4;         // k offset within 16
    const int wr_lane = wr_rl * 4 + ((wr_kk4 & 7) >> 1);
    const int wr_khalf = wr_kk4 >> 3;        // 0,0,1,1

    for (int ch = 0; ch < NCHUNK; ++ch) {
        const int k0 = ch * BK;

        // ---- write X and W tiles into fragment-order smem ----
#pragma unroll
        for (int i = 0; i < 8; ++i) {
            const int rloc  = w * 16 + (i & 1) * 8 + wr_rl;  // row / n (0..127)
            const int kstep = i >> 1;                        // 0..3
            const int c     = k0 + kstep * 16 + wr_kk4;

            // X element (row rloc, k c..c+3)
            const int xrow = rowBase + rloc;
            float4 xv = (xrow < M)
                      ? *(const float4*)(X + (size_t)xrow * IN_DIM + c)
                      : make_float4(0.f, 0.f, 0.f, 0.f);
            uint32_t h0, l0, h1, l1;
            split2(xv.x, xv.y, h0, l0);
            split2(xv.z, xv.w, h1, l1);
            const int rega = (i & 1) + 2 * wr_khalf;
            const int aidx = (w * 4 + kstep) * 136 + rega * 34 + wr_lane;
            smw[SM_AHI + aidx]     = h0;
            smw[SM_AHI + aidx + 1] = h1;
            smw[SM_ALO + aidx]     = l0;
            smw[SM_ALO + aidx + 1] = l1;

            // W element (n rloc, k c..c+3)
            float4 wv = *(const float4*)(W + (size_t)rloc * IN_DIM + c);
            split2(wv.x, wv.y, h0, l0);
            split2(wv.z, wv.w, h1, l1);
            const int atom_b = rloc >> 3;                    // 0..15
            const int bidx = (atom_b * 4 + kstep) * 72 + wr_khalf * 36
                           + wr_rl * 4 + ((wr_kk4 & 7) >> 1);
            smw[SM_BHI + bidx]     = h0;
            smw[SM_BHI + bidx + 1] = h1;
            smw[SM_BLO + bidx]     = l0;
            smw[SM_BLO + bidx + 1] = l1;
        }
        __syncthreads();

        // ---- compute: 4 ksteps x 16 n-atoms x 3 mma ----
#pragma unroll
        for (int kstep = 0; kstep < 4; ++kstep) {
            uint32_t ah[4], al[4];
            const int abase = (w * 4 + kstep) * 136 + l;
#pragma unroll
            for (int j = 0; j < 4; ++j) {
                ah[j] = smw[SM_AHI + abase + j * 34];
                al[j] = smw[SM_ALO + abase + j * 34];
            }
#pragma unroll
            for (int na = 0; na < 16; ++na) {
                const int bbase = (na * 4 + kstep) * 72 + l;
                uint32_t bh0 = smw[SM_BHI + bbase];
                uint32_t bh1 = smw[SM_BHI + bbase + 36];
                uint32_t bl0 = smw[SM_BLO + bbase];
                uint32_t bl1 = smw[SM_BLO + bbase + 36];
                mma_bf16(d[na], ah, bh0, bh1);   // hi*hi
                mma_bf16(d[na], ah, bl0, bl1);   // hi*lo
                mma_bf16(d[na], al, bh0, bh1);   // lo*hi
            }
        }
        __syncthreads();
    }

    // ---- epilogue: add bias, store to g_H ----
    // D frag: d0,d1 = (row g, col 2t,2t+1); d2,d3 = (row g+8, same cols)
    const int row0 = rowBase + w * 16 + (l >> 2);
    const int row1 = row0 + 8;
#pragma unroll
    for (int na = 0; na < 16; ++na) {
        const int col = na * 8 + (l & 3) * 2;
        float2 bv = *(const float2*)(bias + col);
        if (row0 < M) {
            float2 o = make_float2(d[na][0] + bv.x, d[na][1] + bv.y);
            *(float2*)(g_H + (size_t)row0 * OUT_DIM + col) = o;
        }
        if (row1 < M) {
            float2 o = make_float2(d[na][2] + bv.x, d[na][3] + bv.y);
            *(float2*)(g_H + (size_t)row1 * OUT_DIM + col) = o;
        }
    }
}

// ---------------------------------------------------------------------------
// Edge scatter: out[row] += val * H[col]. 4 edges per warp (MLP=4),
// RED.128 vectorized reductions. At the L2 roofline (~145us).
// ---------------------------------------------------------------------------
#define EDGES_PER_WARP 4

__global__ __launch_bounds__(256) void gcn_scatter_kernel(
    const int*   __restrict__ edge_row,
    const int*   __restrict__ edge_col,
    const float* __restrict__ edge_val,
    float*       __restrict__ out,
    int E)
{
    int warp = (int)((blockIdx.x * (unsigned)blockDim.x + threadIdx.x) >> 5);
    int lane = threadIdx.x & 31;
    int base = warp * EDGES_PER_WARP;
    if (base >= E) return;

    int   r[EDGES_PER_WARP], c[EDGES_PER_WARP];
    float v[EDGES_PER_WARP];
    int nb = min(EDGES_PER_WARP, E - base);

#pragma unroll
    for (int j = 0; j < EDGES_PER_WARP; ++j) {
        int e = base + (j < nb ? j : 0);
        r[j] = __ldg(edge_row + e);
        c[j] = __ldg(edge_col + e);
        v[j] = (j < nb) ? __ldg(edge_val + e) : 0.f;
    }

    float4 h[EDGES_PER_WARP];
#pragma unroll
    for (int j = 0; j < EDGES_PER_WARP; ++j)
        h[j] = *(const float4*)(g_H + (size_t)c[j] * OUT_DIM + lane * 4);

#pragma unroll
    for (int j = 0; j < EDGES_PER_WARP; ++j) {
        float* o = out + (size_t)r[j] * OUT_DIM + lane * 4;
        asm volatile("red.global.add.v4.f32 [%0], {%1, %2, %3, %4};"
                     :: "l"(o), "f"(v[j] * h[j].x), "f"(v[j] * h[j].y),
                        "f"(v[j] * h[j].z), "f"(v[j] * h[j].w)
                     : "memory");
    }
}

// ---------------------------------------------------------------------------
// Launch. Input order (metadata): X, edge_row, edge_col, edge_val, W, b.
// ---------------------------------------------------------------------------
extern "C" void kernel_launch(void* const* d_in, const int* in_sizes, int n_in,
                              void* d_out, int out_size)
{
    const float* X  = (const float*)d_in[0];
    const int*   er = (const int*)d_in[1];
    const int*   ec = (const int*)d_in[2];
    const float* ev = (const float*)d_in[3];
    const float* W  = (const float*)d_in[4];
    const float* b  = (const float*)d_in[5];
    float*      out = (float*)d_out;

    const int M = in_sizes[0] / IN_DIM;   // 100000
    const int E = in_sizes[3];            // 1600000

    cudaFuncSetAttribute(gcn_gemm_tc,
                         cudaFuncAttributeMaxDynamicSharedMemorySize,
                         SM_WORDS * 4);

    cudaMemsetAsync(d_out, 0, (size_t)out_size * sizeof(float));

    gcn_gemm_tc<<<(M + 127) / 128, 256, SM_WORDS * 4>>>(X, W, b, M);

    int blocks = (E + EDGES_PER_WARP * 8 - 1) / (EDGES_PER_WARP * 8);
    gcn_scatter_kernel<<<blocks, 256>>>(er, ec, ev, out, E);
}

// round 8
// speedup vs baseline: 2.0268x; 1.2701x over previous
#include <cuda_runtime.h>
#include <cuda_bf16.h>
#include <cstdint>

#define N_NODES_MAX 100000
#define E_MAX 1600000
#define OUT_DIM 128
#define IN_DIM 256

// Scratch (device globals per harness rules)
__device__ float g_H[(size_t)N_NODES_MAX * OUT_DIM];   // 51.2 MB
__device__ int   g_cnt[N_NODES_MAX];                   // histogram, then cursor
__device__ int   g_start[N_NODES_MAX + 1];             // CSR row offsets
__device__ int   g_bsum[512];                          // scan block sums
__device__ int   g_scol[E_MAX];                        // cols sorted by row
__device__ float g_sval[E_MAX];                        // vals sorted by row

// ===========================================================================
// bf16 split helpers
// ===========================================================================
__device__ __forceinline__ void split2(float a, float b,
                                       uint32_t& hi, uint32_t& lo) {
    __nv_bfloat16 ha = __float2bfloat16_rn(a);
    __nv_bfloat16 hb = __float2bfloat16_rn(b);
    __nv_bfloat16 la = __float2bfloat16_rn(a - __bfloat162float(ha));
    __nv_bfloat16 lb = __float2bfloat16_rn(b - __bfloat162float(hb));
    hi = (uint32_t)__bfloat16_as_ushort(ha)
       | ((uint32_t)__bfloat16_as_ushort(hb) << 16);
    lo = (uint32_t)__bfloat16_as_ushort(la)
       | ((uint32_t)__bfloat16_as_ushort(lb) << 16);
}

__device__ __forceinline__ void mma_bf16(float* d, const uint32_t* a,
                                         uint32_t b0, uint32_t b1) {
    asm volatile(
        "mma.sync.aligned.m16n8k16.row.col.f32.bf16.bf16.f32 "
        "{%0,%1,%2,%3}, {%4,%5,%6,%7}, {%8,%9}, {%0,%1,%2,%3};"
        : "+f"(d[0]), "+f"(d[1]), "+f"(d[2]), "+f"(d[3])
        : "r"(a[0]), "r"(a[1]), "r"(a[2]), "r"(a[3]), "r"(b0), "r"(b1));
}

// ===========================================================================
// GEMM: H[M,128] = X[M,256] @ W[128,256]^T + b   (3-term bf16 split, ~1e-5)
// Same structure as R7 winner: fragment-order smem, conflict-free.
// ===========================================================================
#define BK 64
#define NCHUNK (IN_DIM / BK)

#define SM_AHI 0
#define SM_ALO 4352
#define SM_BHI 8704
#define SM_BLO 13312
#define SM_WORDS 17920           // 71680 bytes

__global__ __launch_bounds__(256) void gcn_gemm_tc(
    const float* __restrict__ X,
    const float* __restrict__ W,
    const float* __restrict__ bias,
    int M)
{
    extern __shared__ uint32_t smw[];
    const int tid = threadIdx.x;
    const int w   = tid >> 5;
    const int l   = tid & 31;
    const int rowBase = blockIdx.x * 128;

    float d[16][4];
#pragma unroll
    for (int na = 0; na < 16; ++na)
#pragma unroll
        for (int j = 0; j < 4; ++j) d[na][j] = 0.f;

    const int wr_rl   = l >> 2;
    const int wr_kk4  = (l & 3) * 4;
    const int wr_lane = wr_rl * 4 + ((wr_kk4 & 7) >> 1);
    const int wr_khalf = wr_kk4 >> 3;

    for (int ch = 0; ch < NCHUNK; ++ch) {
        const int k0 = ch * BK;
#pragma unroll
        for (int i = 0; i < 8; ++i) {
            const int rloc  = w * 16 + (i & 1) * 8 + wr_rl;
            const int kstep = i >> 1;
            const int c     = k0 + kstep * 16 + wr_kk4;

            const int xrow = rowBase + rloc;
            float4 xv = (xrow < M)
                      ? *(const float4*)(X + (size_t)xrow * IN_DIM + c)
                      : make_float4(0.f, 0.f, 0.f, 0.f);
            uint32_t h0, l0, h1, l1;
            split2(xv.x, xv.y, h0, l0);
            split2(xv.z, xv.w, h1, l1);
            const int rega = (i & 1) + 2 * wr_khalf;
            const int aidx = (w * 4 + kstep) * 136 + rega * 34 + wr_lane;
            smw[SM_AHI + aidx]     = h0;
            smw[SM_AHI + aidx + 1] = h1;
            smw[SM_ALO + aidx]     = l0;
            smw[SM_ALO + aidx + 1] = l1;

            float4 wv = *(const float4*)(W + (size_t)rloc * IN_DIM + c);
            split2(wv.x, wv.y, h0, l0);
            split2(wv.z, wv.w, h1, l1);
            const int atom_b = rloc >> 3;
            const int bidx = (atom_b * 4 + kstep) * 72 + wr_khalf * 36
                           + wr_rl * 4 + ((wr_kk4 & 7) >> 1);
            smw[SM_BHI + bidx]     = h0;
            smw[SM_BHI + bidx + 1] = h1;
            smw[SM_BLO + bidx]     = l0;
            smw[SM_BLO + bidx + 1] = l1;
        }
        __syncthreads();

#pragma unroll
        for (int kstep = 0; kstep < 4; ++kstep) {
            uint32_t ah[4], al[4];
            const int abase = (w * 4 + kstep) * 136 + l;
#pragma unroll
            for (int j = 0; j < 4; ++j) {
                ah[j] = smw[SM_AHI + abase + j * 34];
                al[j] = smw[SM_ALO + abase + j * 34];
            }
#pragma unroll
            for (int na = 0; na < 16; ++na) {
                const int bbase = (na * 4 + kstep) * 72 + l;
                uint32_t bh0 = smw[SM_BHI + bbase];
                uint32_t bh1 = smw[SM_BHI + bbase + 36];
                uint32_t bl0 = smw[SM_BLO + bbase];
                uint32_t bl1 = smw[SM_BLO + bbase + 36];
                mma_bf16(d[na], ah, bh0, bh1);
                mma_bf16(d[na], ah, bl0, bl1);
                mma_bf16(d[na], al, bh0, bh1);
            }
        }
        __syncthreads();
    }

    const int row0 = rowBase + w * 16 + (l >> 2);
    const int row1 = row0 + 8;
#pragma unroll
    for (int na = 0; na < 16; ++na) {
        const int col = na * 8 + (l & 3) * 2;
        float2 bv = *(const float2*)(bias + col);
        if (row0 < M) {
            float2 o = make_float2(d[na][0] + bv.x, d[na][1] + bv.y);
            *(float2*)(g_H + (size_t)row0 * OUT_DIM + col) = o;
        }
        if (row1 < M) {
            float2 o = make_float2(d[na][2] + bv.x, d[na][3] + bv.y);
            *(float2*)(g_H + (size_t)row1 * OUT_DIM + col) = o;
        }
    }
}

// ===========================================================================
// CSR build: counting sort of edges by row
// ===========================================================================
__global__ __launch_bounds__(256) void k_zero(int N) {
    int i = blockIdx.x * 256 + threadIdx.x;
    if (i < N) g_cnt[i] = 0;
}

__global__ __launch_bounds__(256) void k_hist(
    const int* __restrict__ er, int E)
{
    int i = blockIdx.x * 256 + threadIdx.x;
    if (i < E) atomicAdd(&g_cnt[er[i]], 1);
}

// per-256-block exclusive scan; block totals to g_bsum
__global__ __launch_bounds__(256) void k_scan1(int N) {
    __shared__ int sh[256];
    int i = blockIdx.x * 256 + threadIdx.x;
    int v = (i < N) ? g_cnt[i] : 0;
    sh[threadIdx.x] = v;
    __syncthreads();
#pragma unroll
    for (int off = 1; off < 256; off <<= 1) {
        int t = (threadIdx.x >= off) ? sh[threadIdx.x - off] : 0;
        __syncthreads();
        sh[threadIdx.x] += t;
        __syncthreads();
    }
    if (i < N) g_start[i] = sh[threadIdx.x] - v;   // exclusive within block
    if (threadIdx.x == 255) g_bsum[blockIdx.x] = sh[255];
}

// exclusive scan of block sums (nb <= 512), single block
__global__ __launch_bounds__(512) void k_scan2(int nb) {
    __shared__ int sh[512];
    int t = threadIdx.x;
    int v = (t < nb) ? g_bsum[t] : 0;
    sh[t] = v;
    __syncthreads();
#pragma unroll
    for (int off = 1; off < 512; off <<= 1) {
        int u = (t >= off) ? sh[t - off] : 0;
        __syncthreads();
        sh[t] += u;
        __syncthreads();
    }
    if (t < nb) g_bsum[t] = sh[t] - v;
}

// add block offsets; init cursors; cap row pointer
__global__ __launch_bounds__(256) void k_scan3(int N, int E) {
    int i = blockIdx.x * 256 + threadIdx.x;
    if (i < N) {
        int s = g_start[i] + g_bsum[i >> 8];
        g_start[i] = s;
        g_cnt[i] = s;                              // cursor
    }
    if (i == 0) g_start[N] = E;
}

__global__ __launch_bounds__(256) void k_fill(
    const int* __restrict__ er, const int* __restrict__ ec,
    const float* __restrict__ ev, int E)
{
    int i = blockIdx.x * 256 + threadIdx.x;
    if (i < E) {
        int pos = atomicAdd(&g_cnt[er[i]], 1);
        g_scol[pos] = ec[i];
        g_sval[pos] = ev[i];
    }
}

// ===========================================================================
// Gather: one warp per node, register accumulation, no atomics.
// Each lane owns one float4 (128 features). 4-deep edge unroll for MLP.
// ===========================================================================
__global__ __launch_bounds__(256) void k_gather(float* __restrict__ out, int N)
{
    int warp = (int)((blockIdx.x * (unsigned)blockDim.x + threadIdx.x) >> 5);
    int lane = threadIdx.x & 31;
    if (warp >= N) return;

    int s = g_start[warp];
    int e = g_start[warp + 1];

    float4 acc = make_float4(0.f, 0.f, 0.f, 0.f);
    int j = s;
    for (; j + 4 <= e; j += 4) {
        int   c0 = g_scol[j],     c1 = g_scol[j + 1];
        int   c2 = g_scol[j + 2], c3 = g_scol[j + 3];
        float v0 = g_sval[j],     v1 = g_sval[j + 1];
        float v2 = g_sval[j + 2], v3 = g_sval[j + 3];
        float4 h0 = *(const float4*)(g_H + (size_t)c0 * OUT_DIM + lane * 4);
        float4 h1 = *(const float4*)(g_H + (size_t)c1 * OUT_DIM + lane * 4);
        float4 h2 = *(const float4*)(g_H + (size_t)c2 * OUT_DIM + lane * 4);
        float4 h3 = *(const float4*)(g_H + (size_t)c3 * OUT_DIM + lane * 4);
        acc.x += v0 * h0.x; acc.y += v0 * h0.y; acc.z += v0 * h0.z; acc.w += v0 * h0.w;
        acc.x += v1 * h1.x; acc.y += v1 * h1.y; acc.z += v1 * h1.z; acc.w += v1 * h1.w;
        acc.x += v2 * h2.x; acc.y += v2 * h2.y; acc.z += v2 * h2.z; acc.w += v2 * h2.w;
        acc.x += v3 * h3.x; acc.y += v3 * h3.y; acc.z += v3 * h3.z; acc.w += v3 * h3.w;
    }
    for (; j < e; ++j) {
        int   c = g_scol[j];
        float v = g_sval[j];
        float4 h = *(const float4*)(g_H + (size_t)c * OUT_DIM + lane * 4);
        acc.x += v * h.x; acc.y += v * h.y; acc.z += v * h.z; acc.w += v * h.w;
    }
    *(float4*)(out + (size_t)warp * OUT_DIM + lane * 4) = acc;
}

// ---------------------------------------------------------------------------
// Launch. Input order (metadata): X, edge_row, edge_col, edge_val, W, b.
// ---------------------------------------------------------------------------
extern "C" void kernel_launch(void* const* d_in, const int* in_sizes, int n_in,
                              void* d_out, int out_size)
{
    const float* X  = (const float*)d_in[0];
    const int*   er = (const int*)d_in[1];
    const int*   ec = (const int*)d_in[2];
    const float* ev = (const float*)d_in[3];
    const float* W  = (const float*)d_in[4];
    const float* b  = (const float*)d_in[5];
    float*      out = (float*)d_out;

    const int M = in_sizes[0] / IN_DIM;     // 100000 (X rows)
    const int E = in_sizes[3];              // 1600000
    const int N = out_size / OUT_DIM;       // 100000 (output nodes)

    cudaFuncSetAttribute(gcn_gemm_tc,
                         cudaFuncAttributeMaxDynamicSharedMemorySize,
                         SM_WORDS * 4);

    const int nB  = (N + 255) / 256;        // scan blocks (391)
    const int eB  = (E + 255) / 256;

    // GEMM (independent of CSR build; runs first, overlaps via stream order)
    gcn_gemm_tc<<<(M + 127) / 128, 256, SM_WORDS * 4>>>(X, W, b, M);

    // CSR build
    k_zero <<<nB, 256>>>(N);
    k_hist <<<eB, 256>>>(er, E);
    k_scan1<<<nB, 256>>>(N);
    k_scan2<<<1, 512>>>(nB);
    k_scan3<<<nB, 256>>>(N, E);
    k_fill <<<eB, 256>>>(er, ec, ev, E);

    // gather: warp per node, no atomics, writes every output row
    k_gather<<<(N * 32 + 255) / 256, 256>>>(out, N);
}

// round 9
// speedup vs baseline: 2.2140x; 1.0924x over previous
#include <cuda_runtime.h>
#include <cuda_bf16.h>
#include <cstdint>

#define N_NODES_MAX 100000
#define E_MAX 1600000
#define OUT_DIM 128
#define IN_DIM 256

// Scratch (device globals per harness rules)
__device__ float g_H[(size_t)N_NODES_MAX * OUT_DIM];   // 51.2 MB
__device__ int   g_cnt[N_NODES_MAX];                   // histogram, then cursor
__device__ int   g_start[N_NODES_MAX + 1];             // CSR row offsets
__device__ int   g_bsum[512];                          // scan block sums
__device__ int   g_scol[E_MAX];                        // cols sorted by row
__device__ float g_sval[E_MAX];                        // vals sorted by row

// ===========================================================================
// bf16 split helpers
// ===========================================================================
__device__ __forceinline__ void split2(float a, float b,
                                       uint32_t& hi, uint32_t& lo) {
    __nv_bfloat16 ha = __float2bfloat16_rn(a);
    __nv_bfloat16 hb = __float2bfloat16_rn(b);
    __nv_bfloat16 la = __float2bfloat16_rn(a - __bfloat162float(ha));
    __nv_bfloat16 lb = __float2bfloat16_rn(b - __bfloat162float(hb));
    hi = (uint32_t)__bfloat16_as_ushort(ha)
       | ((uint32_t)__bfloat16_as_ushort(hb) << 16);
    lo = (uint32_t)__bfloat16_as_ushort(la)
       | ((uint32_t)__bfloat16_as_ushort(lb) << 16);
}

__device__ __forceinline__ void mma_bf16(float* d, const uint32_t* a,
                                         uint32_t b0, uint32_t b1) {
    asm volatile(
        "mma.sync.aligned.m16n8k16.row.col.f32.bf16.bf16.f32 "
        "{%0,%1,%2,%3}, {%4,%5,%6,%7}, {%8,%9}, {%0,%1,%2,%3};"
        : "+f"(d[0]), "+f"(d[1]), "+f"(d[2]), "+f"(d[3])
        : "r"(a[0]), "r"(a[1]), "r"(a[2]), "r"(a[3]), "r"(b0), "r"(b1));
}

// ===========================================================================
// GEMM: H[M,128] = X[M,256] @ W[128,256]^T + b   (3-term bf16 split, ~1e-5)
// BK=32, DOUBLE-BUFFERED: stage chunk ch+1 LDGs -> MMA chunk ch from buf A
// -> convert/store chunk ch+1 into buf B -> one sync. Fragment-order smem
// (conflict-free, verified in R7).
// Per buffer (words): AHI 0, ALO 2176, BHI 4352, BLO 6656; size 8960.
// ===========================================================================
#define BK 32
#define NCHUNK (IN_DIM / BK)     // 8

#define BUF_WORDS 8960
#define SM_AHI 0
#define SM_ALO 2176
#define SM_BHI 4352
#define SM_BLO 6656
#define SM_WORDS (2 * BUF_WORDS)   // 17920 words = 71680 bytes

__global__ __launch_bounds__(256) void gcn_gemm_tc(
    const float* __restrict__ X,
    const float* __restrict__ W,
    const float* __restrict__ bias,
    int M)
{
    extern __shared__ uint32_t smw[];
    const int tid = threadIdx.x;
    const int w   = tid >> 5;
    const int l   = tid & 31;
    const int rowBase = blockIdx.x * 128;

    float d[16][4];
#pragma unroll
    for (int na = 0; na < 16; ++na)
#pragma unroll
        for (int j = 0; j < 4; ++j) d[na][j] = 0.f;

    const int wr_rl    = l >> 2;
    const int wr_kk4   = (l & 3) * 4;
    const int wr_lane  = wr_rl * 4 + ((wr_kk4 & 7) >> 1);
    const int wr_khalf = wr_kk4 >> 3;

    float4 xq[4], wq[4];

    // ---- stage chunk 0 ----
#pragma unroll
    for (int i = 0; i < 4; ++i) {
        const int rloc  = w * 16 + (i & 1) * 8 + wr_rl;
        const int kstep = i >> 1;
        const int c     = kstep * 16 + wr_kk4;
        const int xrow  = rowBase + rloc;
        xq[i] = (xrow < M) ? *(const float4*)(X + (size_t)xrow * IN_DIM + c)
                           : make_float4(0.f, 0.f, 0.f, 0.f);
        wq[i] = *(const float4*)(W + (size_t)rloc * IN_DIM + c);
    }
    // ---- store chunk 0 into buf 0 ----
#pragma unroll
    for (int i = 0; i < 4; ++i) {
        const int kstep = i >> 1;
        const int rega  = (i & 1) + 2 * wr_khalf;
        uint32_t h0, l0, h1, l1;
        split2(xq[i].x, xq[i].y, h0, l0);
        split2(xq[i].z, xq[i].w, h1, l1);
        const int aidx = (w * 2 + kstep) * 136 + rega * 34 + wr_lane;
        smw[SM_AHI + aidx]     = h0;
        smw[SM_AHI + aidx + 1] = h1;
        smw[SM_ALO + aidx]     = l0;
        smw[SM_ALO + aidx + 1] = l1;

        const int rloc   = w * 16 + (i & 1) * 8 + wr_rl;
        const int atom_b = rloc >> 3;
        split2(wq[i].x, wq[i].y, h0, l0);
        split2(wq[i].z, wq[i].w, h1, l1);
        const int bidx = (atom_b * 2 + kstep) * 72 + wr_khalf * 36
                       + wr_rl * 4 + ((wr_kk4 & 7) >> 1);
        smw[SM_BHI + bidx]     = h0;
        smw[SM_BHI + bidx + 1] = h1;
        smw[SM_BLO + bidx]     = l0;
        smw[SM_BLO + bidx + 1] = l1;
    }
    __syncthreads();

    for (int ch = 0; ch < NCHUNK; ++ch) {
        const int cur = (ch & 1) * BUF_WORDS;

        // ---- stage chunk ch+1 (LDGs issue; latency hidden by MMAs) ----
        if (ch + 1 < NCHUNK) {
            const int k0n = (ch + 1) * BK;
#pragma unroll
            for (int i = 0; i < 4; ++i) {
                const int rloc  = w * 16 + (i & 1) * 8 + wr_rl;
                const int kstep = i >> 1;
                const int c     = k0n + kstep * 16 + wr_kk4;
                const int xrow  = rowBase + rloc;
                xq[i] = (xrow < M)
                      ? *(const float4*)(X + (size_t)xrow * IN_DIM + c)
                      : make_float4(0.f, 0.f, 0.f, 0.f);
                wq[i] = *(const float4*)(W + (size_t)rloc * IN_DIM + c);
            }
        }

        // ---- compute from current buffer ----
#pragma unroll
        for (int kstep = 0; kstep < 2; ++kstep) {
            uint32_t ah[4], al[4];
            const int abase = cur + (w * 2 + kstep) * 136 + l;
#pragma unroll
            for (int j = 0; j < 4; ++j) {
                ah[j] = smw[SM_AHI + abase + j * 34];
                al[j] = smw[SM_ALO + abase + j * 34];
            }
#pragma unroll
            for (int na = 0; na < 16; ++na) {
                const int bbase = cur + (na * 2 + kstep) * 72 + l;
                uint32_t bh0 = smw[SM_BHI + bbase];
                uint32_t bh1 = smw[SM_BHI + bbase + 36];
                uint32_t bl0 = smw[SM_BLO + bbase];
                uint32_t bl1 = smw[SM_BLO + bbase + 36];
                mma_bf16(d[na], ah, bh0, bh1);
                mma_bf16(d[na], ah, bl0, bl1);
                mma_bf16(d[na], al, bh0, bh1);
            }
        }

        // ---- convert + store chunk ch+1 into other buffer ----
        if (ch + 1 < NCHUNK) {
            const int nxt = ((ch + 1) & 1) * BUF_WORDS;
#pragma unroll
            for (int i = 0; i < 4; ++i) {
                const int kstep = i >> 1;
                const int rega  = (i & 1) + 2 * wr_khalf;
                uint32_t h0, l0, h1, l1;
                split2(xq[i].x, xq[i].y, h0, l0);
                split2(xq[i].z, xq[i].w, h1, l1);
                const int aidx = nxt + (w * 2 + kstep) * 136 + rega * 34 + wr_lane;
                smw[SM_AHI + aidx]     = h0;
                smw[SM_AHI + aidx + 1] = h1;
                smw[SM_ALO + aidx]     = l0;
                smw[SM_ALO + aidx + 1] = l1;

                const int rloc   = w * 16 + (i & 1) * 8 + wr_rl;
                const int atom_b = rloc >> 3;
                split2(wq[i].x, wq[i].y, h0, l0);
                split2(wq[i].z, wq[i].w, h1, l1);
                const int bidx = nxt + (atom_b * 2 + kstep) * 72 + wr_khalf * 36
                               + wr_rl * 4 + ((wr_kk4 & 7) >> 1);
                smw[SM_BHI + bidx]     = h0;
                smw[SM_BHI + bidx + 1] = h1;
                smw[SM_BLO + bidx]     = l0;
                smw[SM_BLO + bidx + 1] = l1;
            }
        }
        __syncthreads();
    }

    // ---- epilogue ----
    const int row0 = rowBase + w * 16 + (l >> 2);
    const int row1 = row0 + 8;
#pragma unroll
    for (int na = 0; na < 16; ++na) {
        const int col = na * 8 + (l & 3) * 2;
        float2 bv = *(const float2*)(bias + col);
        if (row0 < M) {
            float2 o = make_float2(d[na][0] + bv.x, d[na][1] + bv.y);
            *(float2*)(g_H + (size_t)row0 * OUT_DIM + col) = o;
        }
        if (row1 < M) {
            float2 o = make_float2(d[na][2] + bv.x, d[na][3] + bv.y);
            *(float2*)(g_H + (size_t)row1 * OUT_DIM + col) = o;
        }
    }
}

// ===========================================================================
// CSR build: counting sort of edges by row (unchanged from R8)
// ===========================================================================
__global__ __launch_bounds__(256) void k_zero(int N) {
    int i = blockIdx.x * 256 + threadIdx.x;
    if (i < N) g_cnt[i] = 0;
}

__global__ __launch_bounds__(256) void k_hist(
    const int* __restrict__ er, int E)
{
    int i = blockIdx.x * 256 + threadIdx.x;
    if (i < E) atomicAdd(&g_cnt[er[i]], 1);
}

__global__ __launch_bounds__(256) void k_scan1(int N) {
    __shared__ int sh[256];
    int i = blockIdx.x * 256 + threadIdx.x;
    int v = (i < N) ? g_cnt[i] : 0;
    sh[threadIdx.x] = v;
    __syncthreads();
#pragma unroll
    for (int off = 1; off < 256; off <<= 1) {
        int t = (threadIdx.x >= off) ? sh[threadIdx.x - off] : 0;
        __syncthreads();
        sh[threadIdx.x] += t;
        __syncthreads();
    }
    if (i < N) g_start[i] = sh[threadIdx.x] - v;
    if (threadIdx.x == 255) g_bsum[blockIdx.x] = sh[255];
}

__global__ __launch_bounds__(512) void k_scan2(int nb) {
    __shared__ int sh[512];
    int t = threadIdx.x;
    int v = (t < nb) ? g_bsum[t] : 0;
    sh[t] = v;
    __syncthreads();
#pragma unroll
    for (int off = 1; off < 512; off <<= 1) {
        int u = (t >= off) ? sh[t - off] : 0;
        __syncthreads();
        sh[t] += u;
        __syncthreads();
    }
    if (t < nb) g_bsum[t] = sh[t] - v;
}

__global__ __launch_bounds__(256) void k_scan3(int N, int E) {
    int i = blockIdx.x * 256 + threadIdx.x;
    if (i < N) {
        int s = g_start[i] + g_bsum[i >> 8];
        g_start[i] = s;
        g_cnt[i] = s;
    }
    if (i == 0) g_start[N] = E;
}

__global__ __launch_bounds__(256) void k_fill(
    const int* __restrict__ er, const int* __restrict__ ec,
    const float* __restrict__ ev, int E)
{
    int i = blockIdx.x * 256 + threadIdx.x;
    if (i < E) {
        int pos = atomicAdd(&g_cnt[er[i]], 1);
        g_scol[pos] = ec[i];
        g_sval[pos] = ev[i];
    }
}

// ===========================================================================
// Gather: one warp per node, register accumulation, no atomics.
// ===========================================================================
__global__ __launch_bounds__(256) void k_gather(float* __restrict__ out, int N)
{
    int warp = (int)((blockIdx.x * (unsigned)blockDim.x + threadIdx.x) >> 5);
    int lane = threadIdx.x & 31;
    if (warp >= N) return;

    int s = g_start[warp];
    int e = g_start[warp + 1];

    float4 acc = make_float4(0.f, 0.f, 0.f, 0.f);
    int j = s;
    for (; j + 4 <= e; j += 4) {
        int   c0 = g_scol[j],     c1 = g_scol[j + 1];
        int   c2 = g_scol[j + 2], c3 = g_scol[j + 3];
        float v0 = g_sval[j],     v1 = g_sval[j + 1];
        float v2 = g_sval[j + 2], v3 = g_sval[j + 3];
        float4 h0 = *(const float4*)(g_H + (size_t)c0 * OUT_DIM + lane * 4);
        float4 h1 = *(const float4*)(g_H + (size_t)c1 * OUT_DIM + lane * 4);
        float4 h2 = *(const float4*)(g_H + (size_t)c2 * OUT_DIM + lane * 4);
        float4 h3 = *(const float4*)(g_H + (size_t)c3 * OUT_DIM + lane * 4);
        acc.x += v0 * h0.x; acc.y += v0 * h0.y; acc.z += v0 * h0.z; acc.w += v0 * h0.w;
        acc.x += v1 * h1.x; acc.y += v1 * h1.y; acc.z += v1 * h1.z; acc.w += v1 * h1.w;
        acc.x += v2 * h2.x; acc.y += v2 * h2.y; acc.z += v2 * h2.z; acc.w += v2 * h2.w;
        acc.x += v3 * h3.x; acc.y += v3 * h3.y; acc.z += v3 * h3.z; acc.w += v3 * h3.w;
    }
    for (; j < e; ++j) {
        int   c = g_scol[j];
        float v = g_sval[j];
        float4 h = *(const float4*)(g_H + (size_t)c * OUT_DIM + lane * 4);
        acc.x += v * h.x; acc.y += v * h.y; acc.z += v * h.z; acc.w += v * h.w;
    }
    *(float4*)(out + (size_t)warp * OUT_DIM + lane * 4) = acc;
}

// ---------------------------------------------------------------------------
// Stream/event for graph fork-join (created once at static init; no device
// memory allocation involved).
// ---------------------------------------------------------------------------
static cudaStream_t s_aux;
static cudaEvent_t  ev_fork, ev_join;
namespace {
struct InitOnce {
    InitOnce() {
        cudaStreamCreateWithFlags(&s_aux, cudaStreamNonBlocking);
        cudaEventCreateWithFlags(&ev_fork, cudaEventDisableTiming);
        cudaEventCreateWithFlags(&ev_join, cudaEventDisableTiming);
    }
};
InitOnce g_init_once;
}

// ---------------------------------------------------------------------------
// Launch. Input order (metadata): X, edge_row, edge_col, edge_val, W, b.
// CSR build runs on a forked stream concurrently with the GEMM; both join
// before the gather.
// ---------------------------------------------------------------------------
extern "C" void kernel_launch(void* const* d_in, const int* in_sizes, int n_in,
                              void* d_out, int out_size)
{
    const float* X  = (const float*)d_in[0];
    const int*   er = (const int*)d_in[1];
    const int*   ec = (const int*)d_in[2];
    const float* ev = (const float*)d_in[3];
    const float* W  = (const float*)d_in[4];
    const float* b  = (const float*)d_in[5];
    float*      out = (float*)d_out;

    const int M = in_sizes[0] / IN_DIM;     // 100000
    const int E = in_sizes[3];              // 1600000
    const int N = out_size / OUT_DIM;       // 100000

    cudaFuncSetAttribute(gcn_gemm_tc,
                         cudaFuncAttributeMaxDynamicSharedMemorySize,
                         SM_WORDS * 4);

    const int nB = (N + 255) / 256;
    const int eB = (E + 255) / 256;

    // fork: CSR build on aux stream, concurrent with GEMM on main stream
    cudaEventRecord(ev_fork, 0);
    cudaStreamWaitEvent(s_aux, ev_fork, 0);

    k_zero <<<nB, 256, 0, s_aux>>>(N);
    k_hist <<<eB, 256, 0, s_aux>>>(er, E);
    k_scan1<<<nB, 256, 0, s_aux>>>(N);
    k_scan2<<<1, 512, 0, s_aux>>>(nB);
    k_scan3<<<nB, 256, 0, s_aux>>>(N, E);
    k_fill <<<eB, 256, 0, s_aux>>>(er, ec, ev, E);
    cudaEventRecord(ev_join, s_aux);

    // GEMM on main stream (overlaps with build)
    gcn_gemm_tc<<<(M + 127) / 128, 256, SM_WORDS * 4>>>(X, W, b, M);

    // join, then gather
    cudaStreamWaitEvent(0, ev_join, 0);
    k_gather<<<(N * 32 + 255) / 256, 256>>>(out, N);
}